// round 12
// baseline (speedup 1.0000x reference)
#include <cuda_runtime.h>
#include <cstdint>

#define T_STEPS 2000
#define BATCH   256
#define SEQ     10000
#define KW      5

typedef unsigned long long ull;

// Gate pre-activations a_x[t][b][j], stored so float2 at (t*256+b)*32 + l =
// { a[j=l], a[j=l+32] }. Padded by 2 timesteps for branchless prefetch.
__device__ float g_ax[(size_t)(T_STEPS + 2) * BATCH * 64];

__device__ __forceinline__ float tanhap(float x) {
    float r; asm("tanh.approx.f32 %0, %1;" : "=f"(r) : "f"(x)); return r;
}

// ---- f32x2 packed helpers (sm_103a) --------------------------------------
__device__ __forceinline__ ull pk2(float lo, float hi) {
    ull r; asm("mov.b64 %0, {%1, %2};" : "=l"(r) : "f"(lo), "f"(hi)); return r;
}
__device__ __forceinline__ void upk2(float& lo, float& hi, ull v) {
    asm("mov.b64 {%0, %1}, %2;" : "=f"(lo), "=f"(hi) : "l"(v));
}
__device__ __forceinline__ ull ffma2(ull a, ull b, ull c) {
    ull r; asm("fma.rn.f32x2 %0, %1, %2, %3;" : "=l"(r) : "l"(a), "l"(b), "l"(c)); return r;
}
__device__ __forceinline__ ull fadd2(ull a, ull b) {
    ull r; asm("add.rn.f32x2 %0, %1, %2;" : "=l"(r) : "l"(a), "l"(b)); return r;
}
__device__ __forceinline__ ull fmul2(ull a, ull b) {
    ull r; asm("mul.rn.f32x2 %0, %1, %2;" : "=l"(r) : "l"(a), "l"(b)); return r;
}

__device__ __forceinline__ float sigf_exact(float x) {
    return __fdividef(1.0f, 1.0f + __expf(-x));
}

// ---- ordered smem access ----
__device__ __forceinline__ uint32_t smem_u32(const void* p) {
    uint32_t a;
    asm("{ .reg .u64 t; cvta.to.shared.u64 t, %1; cvt.u32.u64 %0, t; }"
        : "=r"(a) : "l"(p));
    return a;
}
__device__ __forceinline__ void sts_f32(uint32_t a, float v) {
    asm volatile("st.shared.f32 [%0], %1;" :: "r"(a), "f"(v) : "memory");
}
__device__ __forceinline__ void sts_v2(uint32_t a, float x, float y) {
    asm volatile("st.shared.v2.f32 [%0], {%1, %2};" :: "r"(a), "f"(x), "f"(y) : "memory");
}
__device__ __forceinline__ ull lds_u64(uint32_t a) {
    ull v; asm volatile("ld.shared.b64 %0, [%1];" : "=l"(v) : "r"(a) : "memory"); return v;
}
__device__ __forceinline__ float4 lds_v4(uint32_t a) {
    float4 v;
    asm volatile("ld.shared.v4.f32 {%0, %1, %2, %3}, [%4];"
                 : "=f"(v.x), "=f"(v.y), "=f"(v.z), "=f"(v.w) : "r"(a) : "memory");
    return v;
}

// ---------------------------------------------------------------------------
// Pre-pass: one THREAD per (t, b); warp covers 32 consecutive t of one b.
// R12: loop-reordered matvec — ONE live accumulator instead of 32 ull
// (cuts register pressure; raw y pairs staged in smem, LN scale applied in a
// second pass after r is known).
// ---------------------------------------------------------------------------
__global__ void __launch_bounds__(128) prepass_kernel(
    const float* __restrict__ x,  const float* __restrict__ Wm,
    const float* __restrict__ bm, const float* __restrict__ Wc,
    const float* __restrict__ bconv, const float* __restrict__ Wx,
    const float* __restrict__ gx, const float* __restrict__ bx,
    const float* __restrict__ bg)
{
    __shared__ float sP[80], sN[80], sbc[16];
    __shared__ float sWm[16], sbm[16], scmx[16];
    __shared__ int   sbmnz;
    __shared__ float sWcT[80 * 16];                 // fallback path only
    __shared__ ull sWxT2[16][32];                   // [o][l] = (WxC[l][o], WxC[l+32][o])
    __shared__ ull sgx2[32], sbxg2[32];
    __shared__ float2 stage[4][32][33];             // [warp][item][pair] (+pad)

    if (threadIdx.x == 0) {
        int nz = 0;
        for (int i = 0; i < 16; i++) if (bm[i] != 0.0f) nz = 1;
        sbmnz = nz;
    }
    if (threadIdx.x < 80) {
        int o = threadIdx.x / 5, k = threadIdx.x % 5;
        float p = 0.0f, n = 0.0f;
        for (int i = 0; i < 16; i++) {
            float w = __ldg(&Wm[i]);
            float c = __ldg(&Wc[o * 80 + i * 5 + k]);
            if (w > 0.0f) p = fmaf(c, w, p);
            else if (w < 0.0f) n = fmaf(c, w, n);
        }
        sP[threadIdx.x] = p;
        sN[threadIdx.x] = n;
    }
    if (threadIdx.x >= 96 && threadIdx.x < 112) {
        int col = threadIdx.x - 96;
        float s = 0.0f;
        for (int j = 0; j < 64; j++) s += __ldg(&Wx[j * 16 + col]);
        scmx[col] = s * (1.0f / 64.0f);
    }
    for (int i = threadIdx.x; i < 16; i += blockDim.x) {
        sbc[i] = bconv[i]; sWm[i] = Wm[i]; sbm[i] = bm[i];
    }
    for (int i = threadIdx.x; i < 80 * 16; i += blockDim.x) {
        int ik = i >> 4, o = i & 15;
        sWcT[i] = Wc[o * 80 + ik];
    }
    for (int i = threadIdx.x; i < 32; i += blockDim.x) {
        sgx2[i]  = pk2(gx[i], gx[i + 32]);
        sbxg2[i] = pk2(bx[i] + bg[i], bx[i + 32] + bg[i + 32]);
    }
    __syncthreads();

    for (int i = threadIdx.x; i < 16 * 32; i += blockDim.x) {
        int o = i >> 5, l = i & 31;
        sWxT2[o][l] = pk2(Wx[l * 16 + o] - scmx[o],
                          Wx[(l + 32) * 16 + o] - scmx[o]);
    }
    __syncthreads();

    const int bmnz = sbmnz;
    int lane = threadIdx.x & 31;
    int wrp  = threadIdx.x >> 5;
    int b    = blockIdx.y;
    int tbase = blockIdx.x * 128 + wrp * 32;
    int t     = tbase + lane;
    int tt = (t < T_STEPS) ? t : 0;

    float xt[16];
    #pragma unroll
    for (int o = 0; o < 16; o++) xt[o] = sbc[o];

    if (!bmnz) {
        #pragma unroll
        for (int k = 0; k < KW; k++) {
            float xk = __ldg(&x[b * SEQ + tt * KW + k]);
            const float* PN = (xk > 0.0f) ? sP : sN;
            #pragma unroll
            for (int o = 0; o < 16; o++)
                xt[o] = fmaf(xk, PN[o * 5 + k], xt[o]);
        }
    } else {
        #pragma unroll
        for (int k = 0; k < KW; k++) {
            float xk = __ldg(&x[b * SEQ + tt * KW + k]);
            #pragma unroll
            for (int i = 0; i < 16; i++) {
                float f = fmaxf(fmaf(xk, sWm[i], sbm[i]), 0.0f);
                const float4* wr = (const float4*)&sWcT[(i * KW + k) * 16];
                #pragma unroll
                for (int o4 = 0; o4 < 4; o4++) {
                    float4 w = wr[o4];
                    xt[o4 * 4 + 0] = fmaf(w.x, f, xt[o4 * 4 + 0]);
                    xt[o4 * 4 + 1] = fmaf(w.y, f, xt[o4 * 4 + 1]);
                    xt[o4 * 4 + 2] = fmaf(w.z, f, xt[o4 * 4 + 2]);
                    xt[o4 * 4 + 3] = fmaf(w.w, f, xt[o4 * 4 + 3]);
                }
            }
        }
    }
    #pragma unroll
    for (int o = 0; o < 16; o++) xt[o] = sigf_exact(xt[o]);

    // packed inputs (x2[o] = (xt_o, xt_o)) — 16 regs of ull
    ull x2[16];
    #pragma unroll
    for (int o = 0; o < 16; o++) x2[o] = pk2(xt[o], xt[o]);

    // y' pairs computed one at a time (loop reorder: one live accumulator),
    // staged raw in smem; q accumulated alongside. mean(y') == 0.
    float2* st = &stage[wrp][lane][0];
    ull q2 = 0ull;
    #pragma unroll
    for (int l = 0; l < 32; l += 2) {
        ull ya = fmul2(sWxT2[0][l],     x2[0]);
        ull yb = fmul2(sWxT2[0][l + 1], x2[0]);
        #pragma unroll
        for (int o = 1; o < 16; o++) {
            ya = ffma2(sWxT2[o][l],     x2[o], ya);
            yb = ffma2(sWxT2[o][l + 1], x2[o], yb);
        }
        float a0, a1, b0, b1;
        upk2(a0, a1, ya); upk2(b0, b1, yb);
        st[l]     = make_float2(a0, a1);
        st[l + 1] = make_float2(b0, b1);
        q2 = ffma2(ya, ya, q2);
        q2 = ffma2(yb, yb, q2);
    }
    float qa, qb;
    upk2(qa, qb, q2);
    float r = rsqrtf((qa + qb) * (1.0f / 64.0f) + 1e-5f);

    // second pass: scale + affine, rewrite stage
    ull r2 = pk2(r, r);
    #pragma unroll
    for (int l = 0; l < 32; l++) {
        float2 v = st[l];
        ull tnorm = fmul2(pk2(v.x, v.y), r2);
        ull a2    = ffma2(tnorm, sgx2[l], sbxg2[l]);
        float a0, a1; upk2(a0, a1, a2);
        st[l] = make_float2(a0, a1);
    }
    __syncwarp();

    float2* gax2 = (float2*)g_ax;
    #pragma unroll 4
    for (int k = 0; k < 32; k++) {
        int tk = tbase + k;
        if (tk < T_STEPS)
            gax2[((size_t)tk * 256 + b) * 32 + lane] = stage[wrp][k][lane];
    }
}

// ---------------------------------------------------------------------------
// Sequential LSTM scan. ONE warp = ONE row; branch-free, sync-free body.
// EXACT R10 structure (scalar lds_u64 gather trees — measured best) plus
// ONLY the constant-folding: "upper ?" scalings folded into per-lane
// constants; post-r chain = FMA -> MUFU -> FMA; off-chain products
// (pya/pyb/k1/k2) computed during the gather-load window.
// ---------------------------------------------------------------------------
__global__ void __launch_bounds__(32) lstm_seq_kernel(
    const float* __restrict__ Wh,   const float* __restrict__ gh,
    const float* __restrict__ bh,   const float* __restrict__ gc,
    const float* __restrict__ bc,   const float* __restrict__ Wcls,
    const float* __restrict__ bcls, const float* __restrict__ h0,
    const float* __restrict__ c0,   float* __restrict__ out)
{
    const unsigned ALL = 0xffffffffu;
    int lane  = threadIdx.x;
    int m     = lane & 15;
    bool upper = lane >= 16;
    int row   = blockIdx.x;

    __shared__ __align__(16) float  smean[16];
    __shared__ __align__(16) float  shv32[32];   // h: all lanes store, read 16..31
    __shared__ __align__(16) float  sqp[32];     // q partials
    __shared__ __align__(16) float2 scq32[32];   // (c, c^2): read 16..31

    // prologue: Wh column means
    {
        float s = 0.0f;
        #pragma unroll 8
        for (int j = 0; j < 64; j++) s += __ldg(&Wh[j * 16 + m]);
        if (!upper) smean[m] = s * (1.0f / 64.0f);
    }
    __syncwarp();

    float wa[16], wb[16];
    #pragma unroll
    for (int i = 0; i < 16; i++) {
        float cm = smean[i];
        wa[i] = __ldg(&Wh[lane * 16 + i]) - cm;
        wb[i] = __ldg(&Wh[(lane + 32) * 16 + i]) - cm;
    }
    // pre-scaled gate constants:
    //   u1 = sig(ga): arg = 0.5*ga
    //   u2 = upper ? sig(gb) : tanh(gb): arg = sgb*gb; out = fmaf(oa, t, ob)
    float sgb = upper ? 0.5f : 1.0f;
    float oa  = upper ? 0.5f : 1.0f;
    float ob  = upper ? 0.5f : 0.0f;
    float ghah = gh[lane] * 0.5f,        bhah = bh[lane] * 0.5f;
    float ghbs = gh[lane + 32] * sgb,    bhbs = bh[lane + 32] * sgb;
    float gcm = gc[m], bcm = bc[m];

    float h = h0[row * 16 + m];
    float c = c0[row * 16 + m];

    uint32_t shv_w = smem_u32(shv32) + lane * 4;
    uint32_t shv_r = smem_u32(shv32) + 64;        // &shv32[16]
    uint32_t sqp_w = smem_u32(sqp) + lane * 4;
    uint32_t sqp_r = smem_u32(sqp);
    uint32_t scq_w = smem_u32(scq32) + lane * 8;
    uint32_t scq_r = smem_u32(scq32) + 128;       // &scq32[16]

    sts_f32(shv_w, h);

    const float2* ax = (const float2*)g_ax;
    const int stride = BATCH * 32;
    const float2* pf = ax + row * 32 + lane;
    float2 p0 = pf[0];
    float2 p1 = pf[stride];
    pf += 2 * stride;

    #pragma unroll 2
    for (int t = 0; t < T_STEPS; t++) {
        // --- h broadcast: 4x LDS.128 from slots 16..31 ---
        float4 hv0 = lds_v4(shv_r);
        float4 hv1 = lds_v4(shv_r + 16);
        float4 hv2 = lds_v4(shv_r + 32);
        float4 hv3 = lds_v4(shv_r + 48);

        float2 cur = p0;
        p0 = p1;
        p1 = *pf;
        pf += stride;

        // --- centered matvec (4 independent FMA chains) ---
        float ya0, ya1, yb0, yb1;
        ya0 = wa[0] * hv0.x; ya1 = wa[1] * hv0.y;
        yb0 = wb[0] * hv0.x; yb1 = wb[1] * hv0.y;
        ya0 = fmaf(wa[2],  hv0.z, ya0); ya1 = fmaf(wa[3],  hv0.w, ya1);
        yb0 = fmaf(wb[2],  hv0.z, yb0); yb1 = fmaf(wb[3],  hv0.w, yb1);
        ya0 = fmaf(wa[4],  hv1.x, ya0); ya1 = fmaf(wa[5],  hv1.y, ya1);
        yb0 = fmaf(wb[4],  hv1.x, yb0); yb1 = fmaf(wb[5],  hv1.y, yb1);
        ya0 = fmaf(wa[6],  hv1.z, ya0); ya1 = fmaf(wa[7],  hv1.w, ya1);
        yb0 = fmaf(wb[6],  hv1.z, yb0); yb1 = fmaf(wb[7],  hv1.w, yb1);
        ya0 = fmaf(wa[8],  hv2.x, ya0); ya1 = fmaf(wa[9],  hv2.y, ya1);
        yb0 = fmaf(wb[8],  hv2.x, yb0); yb1 = fmaf(wb[9],  hv2.y, yb1);
        ya0 = fmaf(wa[10], hv2.z, ya0); ya1 = fmaf(wa[11], hv2.w, ya1);
        yb0 = fmaf(wb[10], hv2.z, yb0); yb1 = fmaf(wb[11], hv2.w, yb1);
        ya0 = fmaf(wa[12], hv3.x, ya0); ya1 = fmaf(wa[13], hv3.y, ya1);
        yb0 = fmaf(wb[12], hv3.x, yb0); yb1 = fmaf(wb[13], hv3.y, yb1);
        ya0 = fmaf(wa[14], hv3.z, ya0); ya1 = fmaf(wa[15], hv3.w, ya1);
        yb0 = fmaf(wb[14], hv3.z, yb0); yb1 = fmaf(wb[15], hv3.w, yb1);
        float ya = ya0 + ya1;
        float yb = yb0 + yb1;

        // --- var reduction (gather1): STS then 16 scalar LDS.64 tree ---
        sts_f32(sqp_w, fmaf(ya, ya, yb * yb));
        ull t0 = fadd2(lds_u64(sqp_r),       lds_u64(sqp_r + 8));
        ull t1 = fadd2(lds_u64(sqp_r + 16),  lds_u64(sqp_r + 24));
        ull t2 = fadd2(lds_u64(sqp_r + 32),  lds_u64(sqp_r + 40));
        ull t3 = fadd2(lds_u64(sqp_r + 48),  lds_u64(sqp_r + 56));
        ull t4 = fadd2(lds_u64(sqp_r + 64),  lds_u64(sqp_r + 72));
        ull t5 = fadd2(lds_u64(sqp_r + 80),  lds_u64(sqp_r + 88));
        ull t6 = fadd2(lds_u64(sqp_r + 96),  lds_u64(sqp_r + 104));
        ull t7 = fadd2(lds_u64(sqp_r + 112), lds_u64(sqp_r + 120));

        // off-chain gate prep (issues during the gather-load window)
        float pya = ya * ghah;                 // ya * gh/2
        float pyb = yb * ghbs;                 // yb * gh*sgb
        float k1  = fmaf(cur.x, 0.5f, bhah);   // (bh + a_x)/2
        float k2  = fmaf(cur.y, sgb,  bhbs);   // (bh + a_x)*sgb

        t0 = fadd2(t0, t1); t2 = fadd2(t2, t3);
        t4 = fadd2(t4, t5); t6 = fadd2(t6, t7);
        t0 = fadd2(fadd2(t0, t2), fadd2(t4, t6));
        float qlo, qhi; upk2(qlo, qhi, t0);
        float r = rsqrtf((qlo + qhi) * (1.0f / 64.0f) + 1e-5f);

        // post-r chain: one FMA each -> MUFU -> one FMA
        float u1 = fmaf(0.5f, tanhap(fmaf(pya, r, k1)), 0.5f);  // sig(i)|sig(f)
        float u2 = fmaf(oa,   tanhap(fmaf(pyb, r, k2)), ob);    // tanh(g)|sig(o)
        float Aval = u1 * u2;                                   // lower: sig(i)tanh(g)
        float A = __shfl_xor_sync(ALL, Aval, 16);

        c = fmaf(u1, c, A);                                     // valid on upper
        sts_v2(scq_w, c, c * c);

        // --- LN16 stats (gather2): 16 scalar LDS.64 tree ---
        ull s0 = fadd2(lds_u64(scq_r),       lds_u64(scq_r + 8));
        ull s1 = fadd2(lds_u64(scq_r + 16),  lds_u64(scq_r + 24));
        ull s2 = fadd2(lds_u64(scq_r + 32),  lds_u64(scq_r + 40));
        ull s3 = fadd2(lds_u64(scq_r + 48),  lds_u64(scq_r + 56));
        ull s4 = fadd2(lds_u64(scq_r + 64),  lds_u64(scq_r + 72));
        ull s5 = fadd2(lds_u64(scq_r + 80),  lds_u64(scq_r + 88));
        ull s6 = fadd2(lds_u64(scq_r + 96),  lds_u64(scq_r + 104));
        ull s7 = fadd2(lds_u64(scq_r + 112), lds_u64(scq_r + 120));
        s0 = fadd2(s0, s1); s2 = fadd2(s2, s3);
        s4 = fadd2(s4, s5); s6 = fadd2(s6, s7);
        s0 = fadd2(fadd2(s0, s2), fadd2(s4, s6));
        float sc, qc; upk2(sc, qc, s0);

        float mc = sc * (1.0f / 16.0f);
        float vc = fmaf(-mc, mc, qc * (1.0f / 16.0f));
        float rc = rsqrtf(vc + 1e-5f);
        float dcg = (c - mc) * gcm;            // off-chain: overlaps the rsqrt
        float cn = fmaf(dcg, rc, bcm);
        h = u2 * tanhap(cn);                   // sig(o)*tanh(cn), upper valid
        sts_f32(shv_w, h);
    }

    // classifier
    float v = upper ? h * Wcls[m] : 0.0f;
    #pragma unroll
    for (int d = 16; d >= 1; d >>= 1)
        v += __shfl_xor_sync(ALL, v, d);
    if (lane == 0)
        out[row] = sigf_exact(v + bcls[0]);
}

// ---------------------------------------------------------------------------
extern "C" void kernel_launch(void* const* d_in, const int* in_sizes, int n_in,
                              void* d_out, int out_size)
{
    const float* x     = (const float*)d_in[0];
    const float* Wm    = (const float*)d_in[1];
    const float* bm    = (const float*)d_in[2];
    const float* Wc    = (const float*)d_in[3];
    const float* bconv = (const float*)d_in[4];
    const float* Wx    = (const float*)d_in[5];
    const float* Wh    = (const float*)d_in[6];
    const float* bg    = (const float*)d_in[7];
    const float* gx    = (const float*)d_in[8];
    const float* bx    = (const float*)d_in[9];
    const float* gh    = (const float*)d_in[10];
    const float* bh    = (const float*)d_in[11];
    const float* gc    = (const float*)d_in[12];
    const float* bc    = (const float*)d_in[13];
    const float* Wcls  = (const float*)d_in[14];
    const float* bcls  = (const float*)d_in[15];
    const float* h0    = (const float*)d_in[16];
    const float* c0    = (const float*)d_in[17];
    float* out = (float*)d_out;

    dim3 pgrid((T_STEPS + 127) / 128, BATCH);
    prepass_kernel<<<pgrid, 128>>>(x, Wm, bm, Wc, bconv, Wx, gx, bx, bg);
    lstm_seq_kernel<<<BATCH, 32>>>(Wh, gh, bh, gc, bc, Wcls, bcls, h0, c0, out);
}

// round 13
// speedup vs baseline: 1.0703x; 1.0703x over previous
#include <cuda_runtime.h>
#include <cstdint>

#define T_STEPS 2000
#define BATCH   256
#define SEQ     10000
#define KW      5

typedef unsigned long long ull;

// Gate pre-activations a_x[t][b][j], stored so float2 at (t*256+b)*32 + l =
// { a[j=l], a[j=l+32] }. Padded by 2 timesteps for branchless prefetch.
__device__ float g_ax[(size_t)(T_STEPS + 2) * BATCH * 64];

__device__ __forceinline__ float tanhap(float x) {
    float r; asm("tanh.approx.f32 %0, %1;" : "=f"(r) : "f"(x)); return r;
}

// ---- f32x2 packed helpers (sm_103a) --------------------------------------
__device__ __forceinline__ ull pk2(float lo, float hi) {
    ull r; asm("mov.b64 %0, {%1, %2};" : "=l"(r) : "f"(lo), "f"(hi)); return r;
}
__device__ __forceinline__ void upk2(float& lo, float& hi, ull v) {
    asm("mov.b64 {%0, %1}, %2;" : "=f"(lo), "=f"(hi) : "l"(v));
}
__device__ __forceinline__ ull ffma2(ull a, ull b, ull c) {
    ull r; asm("fma.rn.f32x2 %0, %1, %2, %3;" : "=l"(r) : "l"(a), "l"(b), "l"(c)); return r;
}
__device__ __forceinline__ ull fadd2(ull a, ull b) {
    ull r; asm("add.rn.f32x2 %0, %1, %2;" : "=l"(r) : "l"(a), "l"(b)); return r;
}
__device__ __forceinline__ ull fmul2(ull a, ull b) {
    ull r; asm("mul.rn.f32x2 %0, %1, %2;" : "=l"(r) : "l"(a), "l"(b)); return r;
}

__device__ __forceinline__ float sigf_exact(float x) {
    return __fdividef(1.0f, 1.0f + __expf(-x));
}

// ---- ordered smem access ----
__device__ __forceinline__ uint32_t smem_u32(const void* p) {
    uint32_t a;
    asm("{ .reg .u64 t; cvta.to.shared.u64 t, %1; cvt.u32.u64 %0, t; }"
        : "=r"(a) : "l"(p));
    return a;
}
__device__ __forceinline__ void sts_f32(uint32_t a, float v) {
    asm volatile("st.shared.f32 [%0], %1;" :: "r"(a), "f"(v) : "memory");
}
__device__ __forceinline__ void sts_v2(uint32_t a, float x, float y) {
    asm volatile("st.shared.v2.f32 [%0], {%1, %2};" :: "r"(a), "f"(x), "f"(y) : "memory");
}
__device__ __forceinline__ float lds_f32(uint32_t a) {
    float v; asm volatile("ld.shared.f32 %0, [%1];" : "=f"(v) : "r"(a) : "memory"); return v;
}
__device__ __forceinline__ ull lds_u64(uint32_t a) {
    ull v; asm volatile("ld.shared.b64 %0, [%1];" : "=l"(v) : "r"(a) : "memory"); return v;
}
__device__ __forceinline__ float4 lds_v4(uint32_t a) {
    float4 v;
    asm volatile("ld.shared.v4.f32 {%0, %1, %2, %3}, [%4];"
                 : "=f"(v.x), "=f"(v.y), "=f"(v.z), "=f"(v.w) : "r"(a) : "memory");
    return v;
}

// ---------------------------------------------------------------------------
// Pre-pass (R12 version, measured neutral vs R10): one THREAD per (t, b).
// ---------------------------------------------------------------------------
__global__ void __launch_bounds__(128) prepass_kernel(
    const float* __restrict__ x,  const float* __restrict__ Wm,
    const float* __restrict__ bm, const float* __restrict__ Wc,
    const float* __restrict__ bconv, const float* __restrict__ Wx,
    const float* __restrict__ gx, const float* __restrict__ bx,
    const float* __restrict__ bg)
{
    __shared__ float sP[80], sN[80], sbc[16];
    __shared__ float sWm[16], sbm[16], scmx[16];
    __shared__ int   sbmnz;
    __shared__ float sWcT[80 * 16];
    __shared__ ull sWxT2[16][32];
    __shared__ ull sgx2[32], sbxg2[32];
    __shared__ float2 stage[4][32][33];

    if (threadIdx.x == 0) {
        int nz = 0;
        for (int i = 0; i < 16; i++) if (bm[i] != 0.0f) nz = 1;
        sbmnz = nz;
    }
    if (threadIdx.x < 80) {
        int o = threadIdx.x / 5, k = threadIdx.x % 5;
        float p = 0.0f, n = 0.0f;
        for (int i = 0; i < 16; i++) {
            float w = __ldg(&Wm[i]);
            float c = __ldg(&Wc[o * 80 + i * 5 + k]);
            if (w > 0.0f) p = fmaf(c, w, p);
            else if (w < 0.0f) n = fmaf(c, w, n);
        }
        sP[threadIdx.x] = p;
        sN[threadIdx.x] = n;
    }
    if (threadIdx.x >= 96 && threadIdx.x < 112) {
        int col = threadIdx.x - 96;
        float s = 0.0f;
        for (int j = 0; j < 64; j++) s += __ldg(&Wx[j * 16 + col]);
        scmx[col] = s * (1.0f / 64.0f);
    }
    for (int i = threadIdx.x; i < 16; i += blockDim.x) {
        sbc[i] = bconv[i]; sWm[i] = Wm[i]; sbm[i] = bm[i];
    }
    for (int i = threadIdx.x; i < 80 * 16; i += blockDim.x) {
        int ik = i >> 4, o = i & 15;
        sWcT[i] = Wc[o * 80 + ik];
    }
    for (int i = threadIdx.x; i < 32; i += blockDim.x) {
        sgx2[i]  = pk2(gx[i], gx[i + 32]);
        sbxg2[i] = pk2(bx[i] + bg[i], bx[i + 32] + bg[i + 32]);
    }
    __syncthreads();

    for (int i = threadIdx.x; i < 16 * 32; i += blockDim.x) {
        int o = i >> 5, l = i & 31;
        sWxT2[o][l] = pk2(Wx[l * 16 + o] - scmx[o],
                          Wx[(l + 32) * 16 + o] - scmx[o]);
    }
    __syncthreads();

    const int bmnz = sbmnz;
    int lane = threadIdx.x & 31;
    int wrp  = threadIdx.x >> 5;
    int b    = blockIdx.y;
    int tbase = blockIdx.x * 128 + wrp * 32;
    int t     = tbase + lane;
    int tt = (t < T_STEPS) ? t : 0;

    float xt[16];
    #pragma unroll
    for (int o = 0; o < 16; o++) xt[o] = sbc[o];

    if (!bmnz) {
        #pragma unroll
        for (int k = 0; k < KW; k++) {
            float xk = __ldg(&x[b * SEQ + tt * KW + k]);
            const float* PN = (xk > 0.0f) ? sP : sN;
            #pragma unroll
            for (int o = 0; o < 16; o++)
                xt[o] = fmaf(xk, PN[o * 5 + k], xt[o]);
        }
    } else {
        #pragma unroll
        for (int k = 0; k < KW; k++) {
            float xk = __ldg(&x[b * SEQ + tt * KW + k]);
            #pragma unroll
            for (int i = 0; i < 16; i++) {
                float f = fmaxf(fmaf(xk, sWm[i], sbm[i]), 0.0f);
                const float4* wr = (const float4*)&sWcT[(i * KW + k) * 16];
                #pragma unroll
                for (int o4 = 0; o4 < 4; o4++) {
                    float4 w = wr[o4];
                    xt[o4 * 4 + 0] = fmaf(w.x, f, xt[o4 * 4 + 0]);
                    xt[o4 * 4 + 1] = fmaf(w.y, f, xt[o4 * 4 + 1]);
                    xt[o4 * 4 + 2] = fmaf(w.z, f, xt[o4 * 4 + 2]);
                    xt[o4 * 4 + 3] = fmaf(w.w, f, xt[o4 * 4 + 3]);
                }
            }
        }
    }
    #pragma unroll
    for (int o = 0; o < 16; o++) xt[o] = sigf_exact(xt[o]);

    ull x2[16];
    #pragma unroll
    for (int o = 0; o < 16; o++) x2[o] = pk2(xt[o], xt[o]);

    float2* st = &stage[wrp][lane][0];
    ull q2 = 0ull;
    #pragma unroll
    for (int l = 0; l < 32; l += 2) {
        ull ya = fmul2(sWxT2[0][l],     x2[0]);
        ull yb = fmul2(sWxT2[0][l + 1], x2[0]);
        #pragma unroll
        for (int o = 1; o < 16; o++) {
            ya = ffma2(sWxT2[o][l],     x2[o], ya);
            yb = ffma2(sWxT2[o][l + 1], x2[o], yb);
        }
        float a0, a1, b0, b1;
        upk2(a0, a1, ya); upk2(b0, b1, yb);
        st[l]     = make_float2(a0, a1);
        st[l + 1] = make_float2(b0, b1);
        q2 = ffma2(ya, ya, q2);
        q2 = ffma2(yb, yb, q2);
    }
    float qa, qb;
    upk2(qa, qb, q2);
    float r = rsqrtf((qa + qb) * (1.0f / 64.0f) + 1e-5f);

    ull r2 = pk2(r, r);
    #pragma unroll
    for (int l = 0; l < 32; l++) {
        float2 v = st[l];
        ull tnorm = fmul2(pk2(v.x, v.y), r2);
        ull a2    = ffma2(tnorm, sgx2[l], sbxg2[l]);
        float a0, a1; upk2(a0, a1, a2);
        st[l] = make_float2(a0, a1);
    }
    __syncwarp();

    float2* gax2 = (float2*)g_ax;
    #pragma unroll 4
    for (int k = 0; k < 32; k++) {
        int tk = tbase + k;
        if (tk < T_STEPS)
            gax2[((size_t)tk * 256 + b) * 32 + lane] = stage[wrp][k][lane];
    }
}

// ---------------------------------------------------------------------------
// Sequential LSTM scan. ONE warp = ONE row; branch-free, sync-free body.
// R10 gate/tail code VERBATIM (measured best; folding regressed). New in R13:
// the LN64 variance is computed as a quadratic form q = h^T G h with
// G = WhC^T WhC (16x16, prologue-precomputed). Lane l computes
// p_m = h_m * (G h)_m immediately after the h-load, so the q-gather's
// STS->LDS roundtrip overlaps the matvec instead of following it; the
// q tree shrinks to 8 loads over 16 partials.
// ---------------------------------------------------------------------------
__global__ void __launch_bounds__(32) lstm_seq_kernel(
    const float* __restrict__ Wh,   const float* __restrict__ gh,
    const float* __restrict__ bh,   const float* __restrict__ gc,
    const float* __restrict__ bc,   const float* __restrict__ Wcls,
    const float* __restrict__ bcls, const float* __restrict__ h0,
    const float* __restrict__ c0,   float* __restrict__ out)
{
    const unsigned ALL = 0xffffffffu;
    int lane  = threadIdx.x;
    int m     = lane & 15;
    bool upper = lane >= 16;
    int row   = blockIdx.x;

    __shared__ __align__(16) float  smean[16];
    __shared__ __align__(16) float  sWhC[64][16];  // prologue scratch for G
    __shared__ __align__(16) float  shv32[32];     // h: all store, read 16..31
    __shared__ __align__(16) float  sqp[32];       // p partials (q = sum 16..31)
    __shared__ __align__(16) float2 scq32[32];     // (c, c^2): read 16..31

    // prologue: Wh column means
    {
        float s = 0.0f;
        #pragma unroll 8
        for (int j = 0; j < 64; j++) s += __ldg(&Wh[j * 16 + m]);
        if (!upper) smean[m] = s * (1.0f / 64.0f);
    }
    __syncwarp();

    float wa[16], wb[16];
    #pragma unroll
    for (int i = 0; i < 16; i++) {
        float cm = smean[i];
        wa[i] = __ldg(&Wh[lane * 16 + i]) - cm;
        wb[i] = __ldg(&Wh[(lane + 32) * 16 + i]) - cm;
        sWhC[lane][i]      = wa[i];   // rows 0..31
        sWhC[lane + 32][i] = wb[i];   // rows 32..63
    }
    __syncwarp();

    // G row m: gr[k] = sum_j WhC[j][m] * WhC[j][k]  (q = h^T G h)
    float gr[16];
    #pragma unroll
    for (int k = 0; k < 16; k++) gr[k] = 0.0f;
    for (int j = 0; j < 64; j++) {
        float a = sWhC[j][m];
        #pragma unroll
        for (int k = 0; k < 16; k++)
            gr[k] = fmaf(a, sWhC[j][k], gr[k]);
    }

    float gha = gh[lane], ghb = gh[lane + 32];
    float bha = bh[lane], bhb = bh[lane + 32];
    float gcm = gc[m],    bcm = bc[m];

    float h = h0[row * 16 + m];
    float c = c0[row * 16 + m];

    uint32_t shv_w  = smem_u32(shv32) + lane * 4;
    uint32_t shv_r  = smem_u32(shv32) + 64;        // &shv32[16]
    uint32_t shm_r  = shv_r + (m << 2);            // own h slot (upper copy)
    uint32_t sqp_w  = smem_u32(sqp) + lane * 4;
    uint32_t sqp_r16 = smem_u32(sqp) + 64;         // &sqp[16]
    uint32_t scq_w  = smem_u32(scq32) + lane * 8;
    uint32_t scq_r  = smem_u32(scq32) + 128;       // &scq32[16]

    sts_f32(shv_w, h);

    const float2* ax = (const float2*)g_ax;
    const int stride = BATCH * 32;
    const float2* pf = ax + row * 32 + lane;
    float2 p0 = pf[0];
    float2 p1 = pf[stride];
    pf += 2 * stride;

    #pragma unroll 2
    for (int t = 0; t < T_STEPS; t++) {
        // --- h broadcast + own-h scalar ---
        float4 hv0 = lds_v4(shv_r);
        float4 hv1 = lds_v4(shv_r + 16);
        float4 hv2 = lds_v4(shv_r + 32);
        float4 hv3 = lds_v4(shv_r + 48);
        float hm = lds_f32(shm_r);

        // --- q partial FIRST: p_m = h_m * (G h)_m; STS starts the roundtrip
        //     early so it overlaps the matvec below ---
        float q0, q1, q2, q3;
        q0 = gr[0] * hv0.x; q1 = gr[1] * hv0.y;
        q2 = gr[2] * hv0.z; q3 = gr[3] * hv0.w;
        q0 = fmaf(gr[4],  hv1.x, q0); q1 = fmaf(gr[5],  hv1.y, q1);
        q2 = fmaf(gr[6],  hv1.z, q2); q3 = fmaf(gr[7],  hv1.w, q3);
        q0 = fmaf(gr[8],  hv2.x, q0); q1 = fmaf(gr[9],  hv2.y, q1);
        q2 = fmaf(gr[10], hv2.z, q2); q3 = fmaf(gr[11], hv2.w, q3);
        q0 = fmaf(gr[12], hv3.x, q0); q1 = fmaf(gr[13], hv3.y, q1);
        q2 = fmaf(gr[14], hv3.z, q2); q3 = fmaf(gr[15], hv3.w, q3);
        sts_f32(sqp_w, hm * ((q0 + q1) + (q2 + q3)));

        float2 cur = p0;
        p0 = p1;
        p1 = *pf;
        pf += stride;

        // --- centered matvec (4 independent FMA chains) — issues while the
        //     q roundtrip is in flight ---
        float ya0, ya1, yb0, yb1;
        ya0 = wa[0] * hv0.x; ya1 = wa[1] * hv0.y;
        yb0 = wb[0] * hv0.x; yb1 = wb[1] * hv0.y;
        ya0 = fmaf(wa[2],  hv0.z, ya0); ya1 = fmaf(wa[3],  hv0.w, ya1);
        yb0 = fmaf(wb[2],  hv0.z, yb0); yb1 = fmaf(wb[3],  hv0.w, yb1);
        ya0 = fmaf(wa[4],  hv1.x, ya0); ya1 = fmaf(wa[5],  hv1.y, ya1);
        yb0 = fmaf(wb[4],  hv1.x, yb0); yb1 = fmaf(wb[5],  hv1.y, yb1);
        ya0 = fmaf(wa[6],  hv1.z, ya0); ya1 = fmaf(wa[7],  hv1.w, ya1);
        yb0 = fmaf(wb[6],  hv1.z, yb0); yb1 = fmaf(wb[7],  hv1.w, yb1);
        ya0 = fmaf(wa[8],  hv2.x, ya0); ya1 = fmaf(wa[9],  hv2.y, ya1);
        yb0 = fmaf(wb[8],  hv2.x, yb0); yb1 = fmaf(wb[9],  hv2.y, yb1);
        ya0 = fmaf(wa[10], hv2.z, ya0); ya1 = fmaf(wa[11], hv2.w, ya1);
        yb0 = fmaf(wb[10], hv2.z, yb0); yb1 = fmaf(wb[11], hv2.w, yb1);
        ya0 = fmaf(wa[12], hv3.x, ya0); ya1 = fmaf(wa[13], hv3.y, ya1);
        yb0 = fmaf(wb[12], hv3.x, yb0); yb1 = fmaf(wb[13], hv3.y, yb1);
        ya0 = fmaf(wa[14], hv3.z, ya0); ya1 = fmaf(wa[15], hv3.w, ya1);
        yb0 = fmaf(wb[14], hv3.z, yb0); yb1 = fmaf(wb[15], hv3.w, yb1);
        float ya = ya0 + ya1;
        float yb = yb0 + yb1;

        // --- q tree: 8 loads over the 16 upper-slot partials ---
        ull t0 = fadd2(lds_u64(sqp_r16),      lds_u64(sqp_r16 + 8));
        ull t1 = fadd2(lds_u64(sqp_r16 + 16), lds_u64(sqp_r16 + 24));
        ull t2 = fadd2(lds_u64(sqp_r16 + 32), lds_u64(sqp_r16 + 40));
        ull t3 = fadd2(lds_u64(sqp_r16 + 48), lds_u64(sqp_r16 + 56));
        t0 = fadd2(t0, t1);
        t2 = fadd2(t2, t3);
        t0 = fadd2(t0, t2);
        float qlo, qhi; upk2(qlo, qhi, t0);
        float r = rsqrtf((qlo + qhi) * (1.0f / 64.0f) + 1e-5f);

        // --- gates (R10 form, verbatim) ---
        float ga = fmaf(ya * r, gha, bha) + cur.x;   // i | f
        float gb = fmaf(yb * r, ghb, bhb) + cur.y;   // g | o

        float u1 = fmaf(0.5f, tanhap(0.5f * ga), 0.5f);   // sig(i) | sig(f)
        float tb = tanhap(upper ? (0.5f * gb) : gb);
        float u2 = upper ? fmaf(0.5f, tb, 0.5f) : tb;     // sig(o) | tanh(g)
        float Aval = u1 * u2;                             // lower: sig(i)*tanh(g)
        float A = __shfl_xor_sync(ALL, Aval, 16);

        c = fmaf(u1, c, A);                               // valid on upper lanes
        sts_v2(scq_w, c, c * c);

        // --- LN16 stats: 16 scalar LDS.64 tree (R10 verbatim) ---
        ull s0 = fadd2(lds_u64(scq_r),       lds_u64(scq_r + 8));
        ull s1 = fadd2(lds_u64(scq_r + 16),  lds_u64(scq_r + 24));
        ull s2 = fadd2(lds_u64(scq_r + 32),  lds_u64(scq_r + 40));
        ull s3 = fadd2(lds_u64(scq_r + 48),  lds_u64(scq_r + 56));
        ull s4 = fadd2(lds_u64(scq_r + 64),  lds_u64(scq_r + 72));
        ull s5 = fadd2(lds_u64(scq_r + 80),  lds_u64(scq_r + 88));
        ull s6 = fadd2(lds_u64(scq_r + 96),  lds_u64(scq_r + 104));
        ull s7 = fadd2(lds_u64(scq_r + 112), lds_u64(scq_r + 120));
        s0 = fadd2(s0, s1); s2 = fadd2(s2, s3);
        s4 = fadd2(s4, s5); s6 = fadd2(s6, s7);
        s0 = fadd2(fadd2(s0, s2), fadd2(s4, s6));
        float sc, qc; upk2(sc, qc, s0);

        float mc = sc * (1.0f / 16.0f);
        float vc = fmaf(-mc, mc, qc * (1.0f / 16.0f));
        float rc = rsqrtf(vc + 1e-5f);
        float cn = fmaf((c - mc) * rc, gcm, bcm);
        h = u2 * tanhap(cn);                              // sig(o)*tanh(cn)
        sts_f32(shv_w, h);
    }

    // classifier
    float v = upper ? h * Wcls[m] : 0.0f;
    #pragma unroll
    for (int d = 16; d >= 1; d >>= 1)
        v += __shfl_xor_sync(ALL, v, d);
    if (lane == 0)
        out[row] = sigf_exact(v + bcls[0]);
}

// ---------------------------------------------------------------------------
extern "C" void kernel_launch(void* const* d_in, const int* in_sizes, int n_in,
                              void* d_out, int out_size)
{
    const float* x     = (const float*)d_in[0];
    const float* Wm    = (const float*)d_in[1];
    const float* bm    = (const float*)d_in[2];
    const float* Wc    = (const float*)d_in[3];
    const float* bconv = (const float*)d_in[4];
    const float* Wx    = (const float*)d_in[5];
    const float* Wh    = (const float*)d_in[6];
    const float* bg    = (const float*)d_in[7];
    const float* gx    = (const float*)d_in[8];
    const float* bx    = (const float*)d_in[9];
    const float* gh    = (const float*)d_in[10];
    const float* bh    = (const float*)d_in[11];
    const float* gc    = (const float*)d_in[12];
    const float* bc    = (const float*)d_in[13];
    const float* Wcls  = (const float*)d_in[14];
    const float* bcls  = (const float*)d_in[15];
    const float* h0    = (const float*)d_in[16];
    const float* c0    = (const float*)d_in[17];
    float* out = (float*)d_out;

    dim3 pgrid((T_STEPS + 127) / 128, BATCH);
    prepass_kernel<<<pgrid, 128>>>(x, Wm, bm, Wc, bconv, Wx, gx, bx, bg);
    lstm_seq_kernel<<<BATCH, 32>>>(Wh, gh, bh, gc, bc, Wcls, bcls, h0, c0, out);
}

// round 14
// speedup vs baseline: 1.2791x; 1.1951x over previous
#include <cuda_runtime.h>
#include <cstdint>

#define T_STEPS 2000
#define BATCH   256
#define SEQ     10000
#define KW      5
#define NCHUNK  16           // 16 chunks x 128 t  (last chunk: 80 real steps)

typedef unsigned long long ull;

// Gate pre-activations a_x[t][b][j], float2 at (t*256+b)*32 + l =
// { a[j=l], a[j=l+32] }. Padded by 2 timesteps for branchless prefetch.
__device__ float g_ax[(size_t)(T_STEPS + 2) * BATCH * 64];
// producer->consumer flags: flag[chunk*256 + b] = 1 when chunk of row b ready
__device__ int g_flag[NCHUNK * BATCH];

__device__ __forceinline__ float tanhap(float x) {
    float r; asm("tanh.approx.f32 %0, %1;" : "=f"(r) : "f"(x)); return r;
}

// ---- f32x2 packed helpers ----
__device__ __forceinline__ ull pk2(float lo, float hi) {
    ull r; asm("mov.b64 %0, {%1, %2};" : "=l"(r) : "f"(lo), "f"(hi)); return r;
}
__device__ __forceinline__ void upk2(float& lo, float& hi, ull v) {
    asm("mov.b64 {%0, %1}, %2;" : "=f"(lo), "=f"(hi) : "l"(v));
}
__device__ __forceinline__ ull ffma2(ull a, ull b, ull c) {
    ull r; asm("fma.rn.f32x2 %0, %1, %2, %3;" : "=l"(r) : "l"(a), "l"(b), "l"(c)); return r;
}
__device__ __forceinline__ ull fadd2(ull a, ull b) {
    ull r; asm("add.rn.f32x2 %0, %1, %2;" : "=l"(r) : "l"(a), "l"(b)); return r;
}
__device__ __forceinline__ ull fmul2(ull a, ull b) {
    ull r; asm("mul.rn.f32x2 %0, %1, %2;" : "=l"(r) : "l"(a), "l"(b)); return r;
}

__device__ __forceinline__ float sigf_exact(float x) {
    return __fdividef(1.0f, 1.0f + __expf(-x));
}

// ---- ordered smem access ----
__device__ __forceinline__ uint32_t smem_u32(const void* p) {
    uint32_t a;
    asm("{ .reg .u64 t; cvta.to.shared.u64 t, %1; cvt.u32.u64 %0, t; }"
        : "=r"(a) : "l"(p));
    return a;
}
__device__ __forceinline__ void sts_f32(uint32_t a, float v) {
    asm volatile("st.shared.f32 [%0], %1;" :: "r"(a), "f"(v) : "memory");
}
__device__ __forceinline__ void sts_v2(uint32_t a, float x, float y) {
    asm volatile("st.shared.v2.f32 [%0], {%1, %2};" :: "r"(a), "f"(x), "f"(y) : "memory");
}
__device__ __forceinline__ ull lds_u64(uint32_t a) {
    ull v; asm volatile("ld.shared.b64 %0, [%1];" : "=l"(v) : "r"(a) : "memory"); return v;
}
__device__ __forceinline__ float4 lds_v4(uint32_t a) {
    float4 v;
    asm volatile("ld.shared.v4.f32 {%0, %1, %2, %3}, [%4];"
                 : "=f"(v.x), "=f"(v.y), "=f"(v.z), "=f"(v.w) : "r"(a) : "memory");
    return v;
}

// ---- gpu-scope release/acquire flag ops + L1-bypass load ----
__device__ __forceinline__ int ld_acq(const int* p) {
    int v; asm volatile("ld.acquire.gpu.global.b32 %0, [%1];"
                        : "=r"(v) : "l"(p) : "memory"); return v;
}
__device__ __forceinline__ void st_rel(int* p, int v) {
    asm volatile("st.release.gpu.global.b32 [%0], %1;"
                 :: "l"(p), "r"(v) : "memory");
}
__device__ __forceinline__ float2 ldg_cv_f2(const float2* p) {
    float2 v;
    asm volatile("ld.global.cv.v2.f32 {%0, %1}, [%2];"
                 : "=f"(v.x), "=f"(v.y) : "l"(p) : "memory");
    return v;
}

// ===========================================================================
// Fused kernel: blocks [0, 256) = scan rows (warp 0 only);
//               blocks [256, 256+4096) = prepass producers.
// ===========================================================================
__global__ void __launch_bounds__(128) fused_kernel(
    const float* __restrict__ x,    const float* __restrict__ Wm,
    const float* __restrict__ bm,   const float* __restrict__ Wc,
    const float* __restrict__ bconv,const float* __restrict__ Wx,
    const float* __restrict__ gx,   const float* __restrict__ bx,
    const float* __restrict__ bg,
    const float* __restrict__ Wh,   const float* __restrict__ gh,
    const float* __restrict__ bh,   const float* __restrict__ gc,
    const float* __restrict__ bc,   const float* __restrict__ Wcls,
    const float* __restrict__ bcls, const float* __restrict__ h0,
    const float* __restrict__ c0,   float* __restrict__ out)
{
    if (blockIdx.x >= 256) {
        // ===================== PREPASS ROLE =====================
        __shared__ float sP[80], sN[80], sbc[16];
        __shared__ float sWm[16], sbm[16], scmx[16];
        __shared__ int   sbmnz;
        __shared__ float sWcT[80 * 16];
        __shared__ ull sWxT2[16][32];
        __shared__ ull sgx2[32], sbxg2[32];
        __shared__ float2 stage[4][32][33];

        int pb = blockIdx.x - 256;
        int cx = pb >> 8;          // chunk 0..15
        int b  = pb & 255;         // batch row

        if (threadIdx.x == 0) {
            int nz = 0;
            for (int i = 0; i < 16; i++) if (bm[i] != 0.0f) nz = 1;
            sbmnz = nz;
        }
        if (threadIdx.x < 80) {
            int o = threadIdx.x / 5, k = threadIdx.x % 5;
            float p = 0.0f, n = 0.0f;
            for (int i = 0; i < 16; i++) {
                float w = __ldg(&Wm[i]);
                float c = __ldg(&Wc[o * 80 + i * 5 + k]);
                if (w > 0.0f) p = fmaf(c, w, p);
                else if (w < 0.0f) n = fmaf(c, w, n);
            }
            sP[threadIdx.x] = p;
            sN[threadIdx.x] = n;
        }
        if (threadIdx.x >= 96 && threadIdx.x < 112) {
            int col = threadIdx.x - 96;
            float s = 0.0f;
            for (int j = 0; j < 64; j++) s += __ldg(&Wx[j * 16 + col]);
            scmx[col] = s * (1.0f / 64.0f);
        }
        for (int i = threadIdx.x; i < 16; i += blockDim.x) {
            sbc[i] = bconv[i]; sWm[i] = Wm[i]; sbm[i] = bm[i];
        }
        for (int i = threadIdx.x; i < 80 * 16; i += blockDim.x) {
            int ik = i >> 4, o = i & 15;
            sWcT[i] = Wc[o * 80 + ik];
        }
        for (int i = threadIdx.x; i < 32; i += blockDim.x) {
            sgx2[i]  = pk2(gx[i], gx[i + 32]);
            sbxg2[i] = pk2(bx[i] + bg[i], bx[i + 32] + bg[i + 32]);
        }
        __syncthreads();

        for (int i = threadIdx.x; i < 16 * 32; i += blockDim.x) {
            int o = i >> 5, l = i & 31;
            sWxT2[o][l] = pk2(Wx[l * 16 + o] - scmx[o],
                              Wx[(l + 32) * 16 + o] - scmx[o]);
        }
        __syncthreads();

        const int bmnz = sbmnz;
        int lane = threadIdx.x & 31;
        int wrp  = threadIdx.x >> 5;
        int tbase = cx * 128 + wrp * 32;
        int t     = tbase + lane;
        int tt = (t < T_STEPS) ? t : 0;

        float xt[16];
        #pragma unroll
        for (int o = 0; o < 16; o++) xt[o] = sbc[o];

        if (!bmnz) {
            #pragma unroll
            for (int k = 0; k < KW; k++) {
                float xk = __ldg(&x[b * SEQ + tt * KW + k]);
                const float* PN = (xk > 0.0f) ? sP : sN;
                #pragma unroll
                for (int o = 0; o < 16; o++)
                    xt[o] = fmaf(xk, PN[o * 5 + k], xt[o]);
            }
        } else {
            #pragma unroll
            for (int k = 0; k < KW; k++) {
                float xk = __ldg(&x[b * SEQ + tt * KW + k]);
                #pragma unroll
                for (int i = 0; i < 16; i++) {
                    float f = fmaxf(fmaf(xk, sWm[i], sbm[i]), 0.0f);
                    const float4* wr = (const float4*)&sWcT[(i * KW + k) * 16];
                    #pragma unroll
                    for (int o4 = 0; o4 < 4; o4++) {
                        float4 w = wr[o4];
                        xt[o4 * 4 + 0] = fmaf(w.x, f, xt[o4 * 4 + 0]);
                        xt[o4 * 4 + 1] = fmaf(w.y, f, xt[o4 * 4 + 1]);
                        xt[o4 * 4 + 2] = fmaf(w.z, f, xt[o4 * 4 + 2]);
                        xt[o4 * 4 + 3] = fmaf(w.w, f, xt[o4 * 4 + 3]);
                    }
                }
            }
        }
        #pragma unroll
        for (int o = 0; o < 16; o++) xt[o] = sigf_exact(xt[o]);

        ull x2[16];
        #pragma unroll
        for (int o = 0; o < 16; o++) x2[o] = pk2(xt[o], xt[o]);

        float2* st = &stage[wrp][lane][0];
        ull q2 = 0ull;
        #pragma unroll
        for (int l = 0; l < 32; l += 2) {
            ull ya = fmul2(sWxT2[0][l],     x2[0]);
            ull yb = fmul2(sWxT2[0][l + 1], x2[0]);
            #pragma unroll
            for (int o = 1; o < 16; o++) {
                ya = ffma2(sWxT2[o][l],     x2[o], ya);
                yb = ffma2(sWxT2[o][l + 1], x2[o], yb);
            }
            float a0, a1, b0, b1;
            upk2(a0, a1, ya); upk2(b0, b1, yb);
            st[l]     = make_float2(a0, a1);
            st[l + 1] = make_float2(b0, b1);
            q2 = ffma2(ya, ya, q2);
            q2 = ffma2(yb, yb, q2);
        }
        float qa, qb;
        upk2(qa, qb, q2);
        float r = rsqrtf((qa + qb) * (1.0f / 64.0f) + 1e-5f);

        ull r2 = pk2(r, r);
        #pragma unroll
        for (int l = 0; l < 32; l++) {
            float2 v = st[l];
            ull tnorm = fmul2(pk2(v.x, v.y), r2);
            ull a2    = ffma2(tnorm, sgx2[l], sbxg2[l]);
            float a0, a1; upk2(a0, a1, a2);
            st[l] = make_float2(a0, a1);
        }
        __syncwarp();

        float2* gax2 = (float2*)g_ax;
        #pragma unroll 4
        for (int k = 0; k < 32; k++) {
            int tk = tbase + k;
            if (tk < T_STEPS)
                gax2[((size_t)tk * 256 + b) * 32 + lane] = stage[wrp][k][lane];
        }

        // publish: all 4 warps' stores done -> release flag for (cx, b)
        __syncthreads();
        if (threadIdx.x == 0) {
            __threadfence();
            st_rel(&g_flag[cx * 256 + b], 1);
        }
        return;
    }

    // ===================== SCAN ROLE (warp 0 only) =====================
    if (threadIdx.x >= 32) return;

    const unsigned ALL = 0xffffffffu;
    int lane  = threadIdx.x;
    int m     = lane & 15;
    bool upper = lane >= 16;
    int row   = blockIdx.x;

    __shared__ __align__(16) float  smean[16];
    __shared__ __align__(16) float  shv32[32];   // h: all lanes store, read 16..31
    __shared__ __align__(16) float  sqp[32];     // q partials
    __shared__ __align__(16) float2 scq32[32];   // (c, c^2): read 16..31

    // prologue: Wh column means (runs while prepass warms up)
    {
        float s = 0.0f;
        #pragma unroll 8
        for (int j = 0; j < 64; j++) s += __ldg(&Wh[j * 16 + m]);
        if (!upper) smean[m] = s * (1.0f / 64.0f);
    }
    __syncwarp();

    float wa[16], wb[16];
    #pragma unroll
    for (int i = 0; i < 16; i++) {
        float cm = smean[i];
        wa[i] = __ldg(&Wh[lane * 16 + i]) - cm;
        wb[i] = __ldg(&Wh[(lane + 32) * 16 + i]) - cm;
    }
    float gha = gh[lane], ghb = gh[lane + 32];
    float bha = bh[lane], bhb = bh[lane + 32];
    float gcm = gc[m],    bcm = bc[m];

    float h = h0[row * 16 + m];
    float c = c0[row * 16 + m];

    uint32_t shv_w = smem_u32(shv32) + lane * 4;
    uint32_t shv_r = smem_u32(shv32) + 64;        // &shv32[16]
    uint32_t sqp_w = smem_u32(sqp) + lane * 4;
    uint32_t sqp_r = smem_u32(sqp);
    uint32_t scq_w = smem_u32(scq32) + lane * 8;
    uint32_t scq_r = smem_u32(scq32) + 128;       // &scq32[16]

    sts_f32(shv_w, h);

    const float2* ax = (const float2*)g_ax;
    const int stride = BATCH * 32;
    const int base = row * 32 + lane;
    float2 p0, p1;

    for (int ck = 0; ck < NCHUNK; ck++) {
        // wait for this chunk of this row (outside the hot loop)
        const int* fp = &g_flag[ck * 256 + row];
        while (ld_acq(fp) == 0) { }

        // reload prefetch regs with L1-bypassing loads (the branchless
        // prefetch below may have touched these lines before they were
        // written; .cv guarantees fresh data after the acquire)
        int tstart = ck * 128;
        p0 = ldg_cv_f2(ax + (size_t)tstart * stride + base);
        p1 = ldg_cv_f2(ax + (size_t)(tstart + 1) * stride + base);
        const float2* pf = ax + (size_t)(tstart + 2) * stride + base;

        int nsteps = (ck == NCHUNK - 1) ? (T_STEPS - 128 * (NCHUNK - 1)) : 128;

        #pragma unroll 2
        for (int k = 0; k < nsteps; k++) {
            // --- h broadcast: 4x LDS.128 from slots 16..31 ---
            float4 hv0 = lds_v4(shv_r);
            float4 hv1 = lds_v4(shv_r + 16);
            float4 hv2 = lds_v4(shv_r + 32);
            float4 hv3 = lds_v4(shv_r + 48);

            float2 cur = p0;
            p0 = p1;
            p1 = *pf;              // unconditional; padded / re-read via .cv
            pf += stride;

            // --- centered matvec (4 independent FMA chains) ---
            float ya0, ya1, yb0, yb1;
            ya0 = wa[0] * hv0.x; ya1 = wa[1] * hv0.y;
            yb0 = wb[0] * hv0.x; yb1 = wb[1] * hv0.y;
            ya0 = fmaf(wa[2],  hv0.z, ya0); ya1 = fmaf(wa[3],  hv0.w, ya1);
            yb0 = fmaf(wb[2],  hv0.z, yb0); yb1 = fmaf(wb[3],  hv0.w, yb1);
            ya0 = fmaf(wa[4],  hv1.x, ya0); ya1 = fmaf(wa[5],  hv1.y, ya1);
            yb0 = fmaf(wb[4],  hv1.x, yb0); yb1 = fmaf(wb[5],  hv1.y, yb1);
            ya0 = fmaf(wa[6],  hv1.z, ya0); ya1 = fmaf(wa[7],  hv1.w, ya1);
            yb0 = fmaf(wb[6],  hv1.z, yb0); yb1 = fmaf(wb[7],  hv1.w, yb1);
            ya0 = fmaf(wa[8],  hv2.x, ya0); ya1 = fmaf(wa[9],  hv2.y, ya1);
            yb0 = fmaf(wb[8],  hv2.x, yb0); yb1 = fmaf(wb[9],  hv2.y, yb1);
            ya0 = fmaf(wa[10], hv2.z, ya0); ya1 = fmaf(wa[11], hv2.w, ya1);
            yb0 = fmaf(wb[10], hv2.z, yb0); yb1 = fmaf(wb[11], hv2.w, yb1);
            ya0 = fmaf(wa[12], hv3.x, ya0); ya1 = fmaf(wa[13], hv3.y, ya1);
            yb0 = fmaf(wb[12], hv3.x, yb0); yb1 = fmaf(wb[13], hv3.y, yb1);
            ya0 = fmaf(wa[14], hv3.z, ya0); ya1 = fmaf(wa[15], hv3.w, ya1);
            yb0 = fmaf(wb[14], hv3.z, yb0); yb1 = fmaf(wb[15], hv3.w, yb1);
            float ya = ya0 + ya1;
            float yb = yb0 + yb1;

            // --- var reduction: STS then 16 scalar LDS.64 tree ---
            sts_f32(sqp_w, fmaf(ya, ya, yb * yb));
            ull t0 = fadd2(lds_u64(sqp_r),       lds_u64(sqp_r + 8));
            ull t1 = fadd2(lds_u64(sqp_r + 16),  lds_u64(sqp_r + 24));
            ull t2 = fadd2(lds_u64(sqp_r + 32),  lds_u64(sqp_r + 40));
            ull t3 = fadd2(lds_u64(sqp_r + 48),  lds_u64(sqp_r + 56));
            ull t4 = fadd2(lds_u64(sqp_r + 64),  lds_u64(sqp_r + 72));
            ull t5 = fadd2(lds_u64(sqp_r + 80),  lds_u64(sqp_r + 88));
            ull t6 = fadd2(lds_u64(sqp_r + 96),  lds_u64(sqp_r + 104));
            ull t7 = fadd2(lds_u64(sqp_r + 112), lds_u64(sqp_r + 120));
            t0 = fadd2(t0, t1); t2 = fadd2(t2, t3);
            t4 = fadd2(t4, t5); t6 = fadd2(t6, t7);
            t0 = fadd2(fadd2(t0, t2), fadd2(t4, t6));
            float qlo, qhi; upk2(qlo, qhi, t0);
            float r = rsqrtf((qlo + qhi) * (1.0f / 64.0f) + 1e-5f);

            float ga = fmaf(ya * r, gha, bha) + cur.x;   // i | f
            float gb = fmaf(yb * r, ghb, bhb) + cur.y;   // g | o

            float u1 = fmaf(0.5f, tanhap(0.5f * ga), 0.5f);   // sig(i)|sig(f)
            float tb = tanhap(upper ? (0.5f * gb) : gb);
            float u2 = upper ? fmaf(0.5f, tb, 0.5f) : tb;     // sig(o)|tanh(g)
            float Aval = u1 * u2;                             // lower: sig(i)tanh(g)
            float A = __shfl_xor_sync(ALL, Aval, 16);

            c = fmaf(u1, c, A);                               // valid on upper
            sts_v2(scq_w, c, c * c);

            // --- LN16 stats: 16 scalar LDS.64 tree ---
            ull s0 = fadd2(lds_u64(scq_r),       lds_u64(scq_r + 8));
            ull s1 = fadd2(lds_u64(scq_r + 16),  lds_u64(scq_r + 24));
            ull s2 = fadd2(lds_u64(scq_r + 32),  lds_u64(scq_r + 40));
            ull s3 = fadd2(lds_u64(scq_r + 48),  lds_u64(scq_r + 56));
            ull s4 = fadd2(lds_u64(scq_r + 64),  lds_u64(scq_r + 72));
            ull s5 = fadd2(lds_u64(scq_r + 80),  lds_u64(scq_r + 88));
            ull s6 = fadd2(lds_u64(scq_r + 96),  lds_u64(scq_r + 104));
            ull s7 = fadd2(lds_u64(scq_r + 112), lds_u64(scq_r + 120));
            s0 = fadd2(s0, s1); s2 = fadd2(s2, s3);
            s4 = fadd2(s4, s5); s6 = fadd2(s6, s7);
            s0 = fadd2(fadd2(s0, s2), fadd2(s4, s6));
            float sc, qc; upk2(sc, qc, s0);

            float mc = sc * (1.0f / 16.0f);
            float vc = fmaf(-mc, mc, qc * (1.0f / 16.0f));
            float rc = rsqrtf(vc + 1e-5f);
            float cn = fmaf((c - mc) * rc, gcm, bcm);
            h = u2 * tanhap(cn);                              // sig(o)*tanh(cn)
            sts_f32(shv_w, h);
        }
    }

    // classifier
    float v = upper ? h * Wcls[m] : 0.0f;
    #pragma unroll
    for (int d = 16; d >= 1; d >>= 1)
        v += __shfl_xor_sync(ALL, v, d);
    if (lane == 0)
        out[row] = sigf_exact(v + bcls[0]);
}

// ---------------------------------------------------------------------------
extern "C" void kernel_launch(void* const* d_in, const int* in_sizes, int n_in,
                              void* d_out, int out_size)
{
    const float* x     = (const float*)d_in[0];
    const float* Wm    = (const float*)d_in[1];
    const float* bm    = (const float*)d_in[2];
    const float* Wc    = (const float*)d_in[3];
    const float* bconv = (const float*)d_in[4];
    const float* Wx    = (const float*)d_in[5];
    const float* Wh    = (const float*)d_in[6];
    const float* bg    = (const float*)d_in[7];
    const float* gx    = (const float*)d_in[8];
    const float* bx    = (const float*)d_in[9];
    const float* gh    = (const float*)d_in[10];
    const float* bh    = (const float*)d_in[11];
    const float* gc    = (const float*)d_in[12];
    const float* bc    = (const float*)d_in[13];
    const float* Wcls  = (const float*)d_in[14];
    const float* bcls  = (const float*)d_in[15];
    const float* h0    = (const float*)d_in[16];
    const float* c0    = (const float*)d_in[17];
    float* out = (float*)d_out;

    // zero the producer/consumer flags (graph-replay safe; async memset node)
    void* flag_ptr = nullptr;
    cudaGetSymbolAddress(&flag_ptr, g_flag);
    cudaMemsetAsync(flag_ptr, 0, NCHUNK * BATCH * sizeof(int));

    fused_kernel<<<256 + NCHUNK * BATCH, 128>>>(
        x, Wm, bm, Wc, bconv, Wx, gx, bx, bg,
        Wh, gh, bh, gc, bc, Wcls, bcls, h0, c0, out);
}